// round 2
// baseline (speedup 1.0000x reference)
#include <cuda_runtime.h>

// Problem constants
#define DIM_B 8
#define DIM_C 16
#define DIM_H 512
#define DIM_W 512
#define NFFT  512
#define NIMG  (DIM_B * DIM_C)          // 128 images
#define NROWS (NIMG * DIM_H)           // 65536 row-lines
#define INV_SCALE (1.0f / (512.0f * 512.0f))

// Scratch: full complex intermediate [img][h][w], 256 MB. Device global (no cudaMalloc).
__device__ float2 g_scratch[(size_t)NIMG * DIM_H * DIM_W];
// Baked filter: bit-reversed in both axes, transposed to [w_pos][h_pos], scale folded in. 2 MB.
__device__ float2 g_filter[(size_t)DIM_H * DIM_W];

__device__ __forceinline__ float2 cmul(float2 a, float2 b) {
    return make_float2(a.x * b.x - a.y * b.y, a.x * b.y + a.y * b.x);
}

__device__ __forceinline__ int brev9(int v) {
    return (int)(__brev((unsigned)v) >> 23);
}

// Fill twiddle table tw[k] = exp(-2*pi*i*k/512), k in [0,256)
__device__ __forceinline__ void init_tw(float2* tw, int tid) {
    if (tid < 256) {
        float s, c;
        sincosf(-6.283185307179586f * (float)tid / 512.0f, &s, &c);
        tw[tid] = make_float2(c, s);
    }
}

// 512-point FFT in shared memory; 128 threads (lane in [0,128)), 2 butterflies/thread/stage.
// forward (inv=false): DIF, natural input -> bit-reversed output, exp(-i...)
// inverse (inv=true):  DIT, bit-reversed input -> natural output, exp(+i...), UNSCALED
__device__ __forceinline__ void fft512(float2* a, int lane, const float2* tw, bool inv) {
    if (!inv) {
        #pragma unroll
        for (int s = 0; s < 9; ++s) {
            int m = 256 >> s;                 // half-span
            #pragma unroll
            for (int q = 0; q < 2; ++q) {
                int b = lane + q * 128;       // butterfly id 0..255
                int j = b & (m - 1);
                int i = ((b & ~(m - 1)) << 1) | j;
                float2 u = a[i];
                float2 v = a[i + m];
                float2 sum = make_float2(u.x + v.x, u.y + v.y);
                float2 dif = make_float2(u.x - v.x, u.y - v.y);
                float2 w = tw[j << s];        // exp(-2pi i * j/(2m))
                a[i]     = sum;
                a[i + m] = make_float2(dif.x * w.x - dif.y * w.y,
                                       dif.x * w.y + dif.y * w.x);
            }
            __syncthreads();
        }
    } else {
        #pragma unroll
        for (int s = 0; s < 9; ++s) {
            int m = 1 << s;
            #pragma unroll
            for (int q = 0; q < 2; ++q) {
                int b = lane + q * 128;
                int j = b & (m - 1);
                int i = ((b & ~(m - 1)) << 1) | j;
                float2 w = tw[j << (8 - s)];  // conj applied below => exp(+2pi i * j/(2m))
                float2 v = a[i + m];
                float2 t = make_float2(v.x * w.x + v.y * w.y,
                                       v.y * w.x - v.x * w.y);
                float2 u = a[i];
                a[i]     = make_float2(u.x + t.x, u.y + t.y);
                a[i + m] = make_float2(u.x - t.x, u.y - t.y);
            }
            __syncthreads();
        }
    }
}

// ---------------------------------------------------------------------------
// Kernel 0: bake filter into bit-reversed / transposed / pre-scaled table.
// g_filter[pw*512 + ph] = (Hr + i*Hi)[brev(ph)][brev(pw)] * (1/(512*512))
// ---------------------------------------------------------------------------
__global__ void k_bake_filter(const float* __restrict__ Hr, const float* __restrict__ Hi) {
    int i = blockIdx.x * blockDim.x + threadIdx.x;  // 0 .. 262143
    int pw = i >> 9;
    int ph = i & 511;
    int src = brev9(ph) * 512 + brev9(pw);
    g_filter[i] = make_float2(Hr[src] * INV_SCALE, Hi[src] * INV_SCALE);
}

// ---------------------------------------------------------------------------
// Kernel 1: forward FFT along W for every row line (4 lines/block, 512 thr).
// ---------------------------------------------------------------------------
__global__ void __launch_bounds__(512) k_fft_rows(const float* __restrict__ x) {
    __shared__ float2 sd[4][NFFT];
    __shared__ float2 tw[256];
    int tid = threadIdx.x;
    init_tw(tw, tid);
    int slot = tid >> 7;
    int lane = tid & 127;
    long long row = (long long)blockIdx.x * 4 + slot;
    const float* xp = x + row * NFFT;

    #pragma unroll
    for (int k = 0; k < 4; ++k) {
        int idx = lane + k * 128;
        sd[slot][idx] = make_float2(xp[idx], 0.0f);
    }
    __syncthreads();

    fft512(sd[slot], lane, tw, false);   // ends with __syncthreads

    float2* gp = g_scratch + row * NFFT;
    #pragma unroll
    for (int k = 0; k < 4; ++k) {
        int idx = lane + k * 128;
        gp[idx] = sd[slot][idx];
    }
}

// ---------------------------------------------------------------------------
// Kernel 2: per image, per 4-column group: FFT along H (DIF), multiply by
// baked filter (bit-reversed coords on both axes), inverse FFT along H (DIT).
// ---------------------------------------------------------------------------
__global__ void __launch_bounds__(512) k_cols(void) {
    __shared__ float2 sd[4][NFFT];
    __shared__ float2 tw[256];
    int tid = threadIdx.x;
    init_tw(tw, tid);

    int img = blockIdx.x >> 7;            // 0..127
    int w0  = (blockIdx.x & 127) << 2;    // column group base

    // Coalesced-ish strided load: 4 adjacent columns so each 32B sector is full.
    int wi = tid & 3;
    int h0 = tid >> 2;                    // 0..127
    float2* base = g_scratch + (long long)img * DIM_H * DIM_W + w0 + wi;
    #pragma unroll
    for (int k = 0; k < 4; ++k) {
        int h = h0 + k * 128;
        sd[wi][h] = base[(long long)h * DIM_W];
    }
    __syncthreads();

    int slot = tid >> 7;
    int lane = tid & 127;
    fft512(sd[slot], lane, tw, false);

    // Pointwise filter, coalesced read of baked table [w_pos][h_pos].
    const float2* frow = g_filter + (long long)(w0 + slot) * 512;
    #pragma unroll
    for (int k = 0; k < 4; ++k) {
        int p = lane + k * 128;
        sd[slot][p] = cmul(sd[slot][p], frow[p]);
    }
    __syncthreads();

    fft512(sd[slot], lane, tw, true);

    #pragma unroll
    for (int k = 0; k < 4; ++k) {
        int h = h0 + k * 128;
        base[(long long)h * DIM_W] = sd[wi][h];
    }
}

// ---------------------------------------------------------------------------
// Kernel 3: inverse FFT along W for every row line, write real part.
// ---------------------------------------------------------------------------
__global__ void __launch_bounds__(512) k_ifft_rows(float* __restrict__ out) {
    __shared__ float2 sd[4][NFFT];
    __shared__ float2 tw[256];
    int tid = threadIdx.x;
    init_tw(tw, tid);
    int slot = tid >> 7;
    int lane = tid & 127;
    long long row = (long long)blockIdx.x * 4 + slot;
    const float2* gp = g_scratch + row * NFFT;

    #pragma unroll
    for (int k = 0; k < 4; ++k) {
        int idx = lane + k * 128;
        sd[slot][idx] = gp[idx];
    }
    __syncthreads();

    fft512(sd[slot], lane, tw, true);

    float* op = out + row * NFFT;
    #pragma unroll
    for (int k = 0; k < 4; ++k) {
        int idx = lane + k * 128;
        op[idx] = sd[slot][idx].x;
    }
}

// ---------------------------------------------------------------------------
extern "C" void kernel_launch(void* const* d_in, const int* in_sizes, int n_in,
                              void* d_out, int out_size) {
    const float* x  = (const float*)d_in[0];   // [8,16,512,512]
    const float* Hr = (const float*)d_in[1];   // [512,512]
    const float* Hi = (const float*)d_in[2];   // [512,512]
    float* out = (float*)d_out;

    k_bake_filter<<<(DIM_H * DIM_W) / 512, 512>>>(Hr, Hi);
    k_fft_rows<<<NROWS / 4, 512>>>(x);
    k_cols<<<NIMG * (DIM_W / 4), 512>>>();
    k_ifft_rows<<<NROWS / 4, 512>>>(out);
}

// round 3
// speedup vs baseline: 3.4817x; 3.4817x over previous
#include <cuda_runtime.h>

#define DIM_H 512
#define DIM_W 512
#define NIMG  128
#define NROWS (NIMG * DIM_H)           // 65536 row-lines
#define INV_SCALE (1.0f / (512.0f * 512.0f))
#define PL 584                          // shared plane pitch (>=575, ==8 mod 32)

__device__ float2 g_scratch[(size_t)NIMG * DIM_H * DIM_W];   // 256 MB
__device__ float2 g_filter[(size_t)DIM_H * DIM_W];           // 2 MB

__device__ __forceinline__ float2 cadd(float2 a, float2 b){ return make_float2(a.x+b.x, a.y+b.y); }
__device__ __forceinline__ float2 csub(float2 a, float2 b){ return make_float2(a.x-b.x, a.y-b.y); }
__device__ __forceinline__ float2 cmul(float2 a, float2 b){
    return make_float2(a.x*b.x - a.y*b.y, a.x*b.y + a.y*b.x);
}
__device__ __forceinline__ float2 cconj(float2 a){ return make_float2(a.x, -a.y); }

// storage-position -> true-frequency permutation: swap low two octal digits of 9-bit index
__device__ __forceinline__ int kmap9(int p){
    return (p & 448) | ((p & 7) << 3) | ((p >> 3) & 7);
}

// 8-point DFT, natural in/out: out[r] = sum_j in[j] * exp(S*2*pi*i*j*r/8)
template<int S>
__device__ __forceinline__ void dft8(float2* a){
    const float sg = (float)S;
    float2 e0=a[0], e1=a[2], e2=a[4], e3=a[6];
    float2 o0=a[1], o1=a[3], o2=a[5], o3=a[7];
    float2 t0=cadd(e0,e2), t1=csub(e0,e2), t2=cadd(e1,e3), t3=csub(e1,e3);
    float2 t3r = make_float2(-sg*t3.y, sg*t3.x);
    float2 E0=cadd(t0,t2), E2=csub(t0,t2), E1=cadd(t1,t3r), E3=csub(t1,t3r);
    float2 u0=cadd(o0,o2), u1=csub(o0,o2), u2=cadd(o1,o3), u3=csub(o1,o3);
    float2 u3r = make_float2(-sg*u3.y, sg*u3.x);
    float2 O0=cadd(u0,u2), O2=csub(u0,u2), O1=cadd(u1,u3r), O3=csub(u1,u3r);
    const float c = 0.70710678118654752f;
    O1 = make_float2(c*(O1.x - sg*O1.y), c*(sg*O1.x + O1.y));     // * (c + i*S*c)
    O2 = make_float2(-sg*O2.y, sg*O2.x);                          // * (i*S)
    O3 = make_float2(c*(-O3.x - sg*O3.y), c*(sg*O3.x - O3.y));    // * (-c + i*S*c)
    a[0]=cadd(E0,O0); a[4]=csub(E0,O0);
    a[1]=cadd(E1,O1); a[5]=csub(E1,O1);
    a[2]=cadd(E2,O2); a[6]=csub(E2,O2);
    a[3]=cadd(E3,O3); a[7]=csub(E3,O3);
}

// Build twiddle table tws[k] = exp(-2*pi*i*k/512), k in [0,512)
__device__ __forceinline__ void build_tws(float2* tws, int tid){
    if (tid < 256){
        float s, c;
        sincosf(-6.283185307179586f * (float)tid / 512.0f, &s, &c);
        tws[tid] = make_float2(c, s);
        sincosf(-6.283185307179586f * (float)(tid + 256) / 512.0f, &s, &c);
        tws[tid + 256] = make_float2(c, s);
    }
}

// Forward 512-pt FFT. In: a[j] = x[t + 64*j]. Out: a[q] = X[kmap9(t + 64*q)].
// Uses 2 conflict-free shared transposes. Ends without trailing sync (regs valid).
__device__ __forceinline__ void fft512_fwd(float2* a, int line, int t,
                                           float (*sRe)[PL], float (*sIm)[PL],
                                           const float2* tws){
    dft8<-1>(a);
    float2 wb = tws[t], cw = wb;
    a[1] = cmul(a[1], cw);
    #pragma unroll
    for (int r = 2; r < 8; ++r){ cw = cmul(cw, wb); a[r] = cmul(a[r], cw); }
    #pragma unroll
    for (int r = 0; r < 8; ++r){ sRe[line][r*72 + t] = a[r].x; sIm[line][r*72 + t] = a[r].y; }
    __syncthreads();
    int tp = t & 7, rr = t >> 3;
    #pragma unroll
    for (int j = 0; j < 8; ++j){
        int ad = rr*72 + tp + 8*j;
        a[j] = make_float2(sRe[line][ad], sIm[line][ad]);
    }
    dft8<-1>(a);
    float2 wb2 = tws[tp*8]; cw = wb2;
    a[1] = cmul(a[1], cw);
    #pragma unroll
    for (int r = 2; r < 8; ++r){ cw = cmul(cw, wb2); a[r] = cmul(a[r], cw); }
    __syncthreads();
    #pragma unroll
    for (int r1 = 0; r1 < 8; ++r1){
        int ad = rr*72 + r1*9 + tp;
        sRe[line][ad] = a[r1].x; sIm[line][ad] = a[r1].y;
    }
    __syncthreads();
    #pragma unroll
    for (int k = 0; k < 8; ++k){
        int ad = t*9 + k;
        a[k] = make_float2(sRe[line][ad], sIm[line][ad]);
    }
    dft8<-1>(a);
}

// Inverse (unscaled) 512-pt FFT. In: a[q] = S[kmap9(t + 64*q)]. Out: a[j] = y[t + 64*j].
__device__ __forceinline__ void fft512_inv(float2* a, int line, int t,
                                           float (*sRe)[PL], float (*sIm)[PL],
                                           const float2* tws){
    dft8<1>(a);
    int tp = t & 7, rr = t >> 3;
    #pragma unroll
    for (int k = 0; k < 8; ++k){
        int ad = t*9 + k;
        sRe[line][ad] = a[k].x; sIm[line][ad] = a[k].y;
    }
    __syncthreads();
    #pragma unroll
    for (int r1 = 0; r1 < 8; ++r1){
        int ad = rr*72 + r1*9 + tp;
        a[r1] = make_float2(sRe[line][ad], sIm[line][ad]);
    }
    float2 wb2 = cconj(tws[tp*8]), cw = wb2;
    a[1] = cmul(a[1], cw);
    #pragma unroll
    for (int r = 2; r < 8; ++r){ cw = cmul(cw, wb2); a[r] = cmul(a[r], cw); }
    dft8<1>(a);
    __syncthreads();
    #pragma unroll
    for (int j = 0; j < 8; ++j){
        int ad = rr*72 + tp + 8*j;
        sRe[line][ad] = a[j].x; sIm[line][ad] = a[j].y;
    }
    __syncthreads();
    #pragma unroll
    for (int r = 0; r < 8; ++r){
        int ad = r*72 + t;
        a[r] = make_float2(sRe[line][ad], sIm[line][ad]);
    }
    float2 wb = cconj(tws[t]); cw = wb;
    a[1] = cmul(a[1], cw);
    #pragma unroll
    for (int r = 2; r < 8; ++r){ cw = cmul(cw, wb); a[r] = cmul(a[r], cw); }
    dft8<1>(a);
}

// ---------------------------------------------------------------------------
// Kernel 0: bake filter into permuted / transposed / pre-scaled table.
// g_filter[pw*512 + ph] = H[kmap9(ph)][kmap9(pw)] * (1/512^2)
// ---------------------------------------------------------------------------
__global__ void k_bake_filter(const float* __restrict__ Hr, const float* __restrict__ Hi){
    int i = blockIdx.x * blockDim.x + threadIdx.x;
    int pw = i >> 9, ph = i & 511;
    int src = kmap9(ph) * 512 + kmap9(pw);
    g_filter[i] = make_float2(Hr[src] * INV_SCALE, Hi[src] * INV_SCALE);
}

// ---------------------------------------------------------------------------
// Kernel 1: forward FFT along W (4 lines/block, 64 thr/line)
// ---------------------------------------------------------------------------
__global__ void __launch_bounds__(256) k_fft_rows(const float* __restrict__ x){
    __shared__ float sRe[4][PL], sIm[4][PL];
    __shared__ float2 tws[512];
    int tid = threadIdx.x;
    build_tws(tws, tid);
    int line = tid >> 6, t = tid & 63;
    long long row = (long long)blockIdx.x * 4 + line;
    const float* xp = x + row * 512;

    float2 a[8];
    #pragma unroll
    for (int j = 0; j < 8; ++j) a[j] = make_float2(xp[t + 64*j], 0.0f);
    __syncthreads();   // tws ready

    fft512_fwd(a, line, t, sRe, sIm, tws);

    float2* gp = g_scratch + row * 512;
    #pragma unroll
    for (int q = 0; q < 8; ++q) gp[t + 64*q] = a[q];
}

// ---------------------------------------------------------------------------
// Kernel 2: per image, 4 adjacent columns: fwd col FFT -> filter -> inv col FFT
// ---------------------------------------------------------------------------
__global__ void __launch_bounds__(256) k_cols(void){
    __shared__ float sRe[4][PL], sIm[4][PL];
    __shared__ float2 tws[512];
    int tid = threadIdx.x;
    build_tws(tws, tid);

    int img = blockIdx.x >> 7;
    int w0  = (blockIdx.x & 127) << 2;
    float2* base = g_scratch + (long long)img * DIM_H * DIM_W;

    // stage in: coalesced (4 adjacent cols -> full 32B sectors), conflict-free shared write
    #pragma unroll
    for (int it = 0; it < 8; ++it){
        int idx = it * 256 + tid;
        int wi = idx & 3, h = idx >> 2;
        float2 v = base[(long long)h * 512 + w0 + wi];
        sRe[wi][h] = v.x; sIm[wi][h] = v.y;
    }
    __syncthreads();

    int line = tid >> 6, t = tid & 63;
    float2 a[8];
    #pragma unroll
    for (int j = 0; j < 8; ++j){
        int h = t + 64*j;
        a[j] = make_float2(sRe[line][h], sIm[line][h]);
    }
    __syncthreads();   // staging consumed; buffer reusable for transposes

    fft512_fwd(a, line, t, sRe, sIm, tws);

    // pointwise filter in registers (spectrum pos p = t + 64q, coalesced filter read)
    const float2* frow = g_filter + (long long)(w0 + line) * 512 + t;
    #pragma unroll
    for (int q = 0; q < 8; ++q) a[q] = cmul(a[q], frow[64*q]);

    __syncthreads();   // forward's last transpose reads done before inverse writes

    fft512_inv(a, line, t, sRe, sIm, tws);

    __syncthreads();   // inverse's transpose reads done before staging-out writes
    #pragma unroll
    for (int j = 0; j < 8; ++j){
        int h = t + 64*j;
        sRe[line][h] = a[j].x; sIm[line][h] = a[j].y;
    }
    __syncthreads();

    #pragma unroll
    for (int it = 0; it < 8; ++it){
        int idx = it * 256 + tid;
        int wi = idx & 3, h = idx >> 2;
        base[(long long)h * 512 + w0 + wi] = make_float2(sRe[wi][h], sIm[wi][h]);
    }
}

// ---------------------------------------------------------------------------
// Kernel 3: inverse FFT along W, write real part
// ---------------------------------------------------------------------------
__global__ void __launch_bounds__(256) k_ifft_rows(float* __restrict__ out){
    __shared__ float sRe[4][PL], sIm[4][PL];
    __shared__ float2 tws[512];
    int tid = threadIdx.x;
    build_tws(tws, tid);
    int line = tid >> 6, t = tid & 63;
    long long row = (long long)blockIdx.x * 4 + line;
    const float2* gp = g_scratch + row * 512;

    float2 a[8];
    #pragma unroll
    for (int q = 0; q < 8; ++q) a[q] = gp[t + 64*q];
    __syncthreads();   // tws ready

    fft512_inv(a, line, t, sRe, sIm, tws);

    float* op = out + row * 512;
    #pragma unroll
    for (int j = 0; j < 8; ++j) op[t + 64*j] = a[j].x;
}

// ---------------------------------------------------------------------------
extern "C" void kernel_launch(void* const* d_in, const int* in_sizes, int n_in,
                              void* d_out, int out_size){
    const float* x  = (const float*)d_in[0];
    const float* Hr = (const float*)d_in[1];
    const float* Hi = (const float*)d_in[2];
    float* out = (float*)d_out;

    k_bake_filter<<<(DIM_H * DIM_W) / 512, 512>>>(Hr, Hi);
    k_fft_rows<<<NROWS / 4, 256>>>(x);
    k_cols<<<NIMG * (DIM_W / 4), 256>>>();
    k_ifft_rows<<<NROWS / 4, 256>>>(out);
}

// round 4
// speedup vs baseline: 5.1376x; 1.4756x over previous
#include <cuda_runtime.h>

#define DIM_H 512
#define DIM_W 512
#define NIMG  128
#define NROWS (NIMG * DIM_H)           // 65536 row-lines
#define INV_SCALE (1.0f / (512.0f * 512.0f))
#define PL 584                          // shared plane pitch (>=575, ==8 mod 32)
#define WP 264                          // half-spectrum storage pitch (float2), 257 used

// Half-spectrum scratch: [img][h][pw<WP], 138 MB.
__device__ float2 g_scratch[(size_t)NIMG * DIM_H * WP];
// Baked Hermitianized filter, permuted+transposed: [pw 0..256][ph 0..511].
__device__ float2 g_filter[(size_t)257 * DIM_H];

__device__ __forceinline__ float2 cadd(float2 a, float2 b){ return make_float2(a.x+b.x, a.y+b.y); }
__device__ __forceinline__ float2 csub(float2 a, float2 b){ return make_float2(a.x-b.x, a.y-b.y); }
__device__ __forceinline__ float2 cmul(float2 a, float2 b){
    return make_float2(a.x*b.x - a.y*b.y, a.x*b.y + a.y*b.x);
}
__device__ __forceinline__ float2 cconj(float2 a){ return make_float2(a.x, -a.y); }

// storage-position <-> frequency permutation: swap low two octal digits (involution, keeps bit 8)
__device__ __forceinline__ int kmap9(int p){
    return (p & 448) | ((p & 7) << 3) | ((p >> 3) & 7);
}

// 8-point DFT, natural in/out: out[r] = sum_j in[j] * exp(S*2*pi*i*j*r/8)
template<int S>
__device__ __forceinline__ void dft8(float2* a){
    const float sg = (float)S;
    float2 e0=a[0], e1=a[2], e2=a[4], e3=a[6];
    float2 o0=a[1], o1=a[3], o2=a[5], o3=a[7];
    float2 t0=cadd(e0,e2), t1=csub(e0,e2), t2=cadd(e1,e3), t3=csub(e1,e3);
    float2 t3r = make_float2(-sg*t3.y, sg*t3.x);
    float2 E0=cadd(t0,t2), E2=csub(t0,t2), E1=cadd(t1,t3r), E3=csub(t1,t3r);
    float2 u0=cadd(o0,o2), u1=csub(o0,o2), u2=cadd(o1,o3), u3=csub(o1,o3);
    float2 u3r = make_float2(-sg*u3.y, sg*u3.x);
    float2 O0=cadd(u0,u2), O2=csub(u0,u2), O1=cadd(u1,u3r), O3=csub(u1,u3r);
    const float c = 0.70710678118654752f;
    O1 = make_float2(c*(O1.x - sg*O1.y), c*(sg*O1.x + O1.y));
    O2 = make_float2(-sg*O2.y, sg*O2.x);
    O3 = make_float2(c*(-O3.x - sg*O3.y), c*(sg*O3.x - O3.y));
    a[0]=cadd(E0,O0); a[4]=csub(E0,O0);
    a[1]=cadd(E1,O1); a[5]=csub(E1,O1);
    a[2]=cadd(E2,O2); a[6]=csub(E2,O2);
    a[3]=cadd(E3,O3); a[7]=csub(E3,O3);
}

__device__ __forceinline__ void build_tws(float2* tws, int tid){
    if (tid < 256){
        float s, c;
        sincosf(-6.283185307179586f * (float)tid / 512.0f, &s, &c);
        tws[tid] = make_float2(c, s);
        sincosf(-6.283185307179586f * (float)(tid + 256) / 512.0f, &s, &c);
        tws[tid + 256] = make_float2(c, s);
    }
}

// Forward 512-pt FFT. In: a[j] = x[t + 64*j]. Out: a[q] = X[kmap9(t + 64*q)].
__device__ __forceinline__ void fft512_fwd(float2* a, int line, int t,
                                           float (*sRe)[PL], float (*sIm)[PL],
                                           const float2* tws){
    dft8<-1>(a);
    float2 wb = tws[t], cw = wb;
    a[1] = cmul(a[1], cw);
    #pragma unroll
    for (int r = 2; r < 8; ++r){ cw = cmul(cw, wb); a[r] = cmul(a[r], cw); }
    #pragma unroll
    for (int r = 0; r < 8; ++r){ sRe[line][r*72 + t] = a[r].x; sIm[line][r*72 + t] = a[r].y; }
    __syncthreads();
    int tp = t & 7, rr = t >> 3;
    #pragma unroll
    for (int j = 0; j < 8; ++j){
        int ad = rr*72 + tp + 8*j;
        a[j] = make_float2(sRe[line][ad], sIm[line][ad]);
    }
    dft8<-1>(a);
    float2 wb2 = tws[tp*8]; cw = wb2;
    a[1] = cmul(a[1], cw);
    #pragma unroll
    for (int r = 2; r < 8; ++r){ cw = cmul(cw, wb2); a[r] = cmul(a[r], cw); }
    __syncthreads();
    #pragma unroll
    for (int r1 = 0; r1 < 8; ++r1){
        int ad = rr*72 + r1*9 + tp;
        sRe[line][ad] = a[r1].x; sIm[line][ad] = a[r1].y;
    }
    __syncthreads();
    #pragma unroll
    for (int k = 0; k < 8; ++k){
        int ad = t*9 + k;
        a[k] = make_float2(sRe[line][ad], sIm[line][ad]);
    }
    dft8<-1>(a);
}

// Inverse (unscaled) 512-pt FFT. In: a[q] = S[kmap9(t + 64*q)]. Out: a[j] = y[t + 64*j].
__device__ __forceinline__ void fft512_inv(float2* a, int line, int t,
                                           float (*sRe)[PL], float (*sIm)[PL],
                                           const float2* tws){
    dft8<1>(a);
    int tp = t & 7, rr = t >> 3;
    #pragma unroll
    for (int k = 0; k < 8; ++k){
        int ad = t*9 + k;
        sRe[line][ad] = a[k].x; sIm[line][ad] = a[k].y;
    }
    __syncthreads();
    #pragma unroll
    for (int r1 = 0; r1 < 8; ++r1){
        int ad = rr*72 + r1*9 + tp;
        a[r1] = make_float2(sRe[line][ad], sIm[line][ad]);
    }
    float2 wb2 = cconj(tws[tp*8]), cw = wb2;
    a[1] = cmul(a[1], cw);
    #pragma unroll
    for (int r = 2; r < 8; ++r){ cw = cmul(cw, wb2); a[r] = cmul(a[r], cw); }
    dft8<1>(a);
    __syncthreads();
    #pragma unroll
    for (int j = 0; j < 8; ++j){
        int ad = rr*72 + tp + 8*j;
        sRe[line][ad] = a[j].x; sIm[line][ad] = a[j].y;
    }
    __syncthreads();
    #pragma unroll
    for (int r = 0; r < 8; ++r){
        int ad = r*72 + t;
        a[r] = make_float2(sRe[line][ad], sIm[line][ad]);
    }
    float2 wb = cconj(tws[t]); cw = wb;
    a[1] = cmul(a[1], cw);
    #pragma unroll
    for (int r = 2; r < 8; ++r){ cw = cmul(cw, wb); a[r] = cmul(a[r], cw); }
    dft8<1>(a);
}

// ---------------------------------------------------------------------------
// Kernel 0: bake Hermitianized filter.
// Heff[kh][kw] = (H[kh][kw] + conj(H[(-kh)%512][(-kw)%512])) / 2
// g_filter[pw*512 + ph] = Heff[kmap9(ph)][kmap9(pw)] * (1/512^2), pw in [0,257)
// ---------------------------------------------------------------------------
__global__ void k_bake_filter(const float* __restrict__ Hr, const float* __restrict__ Hi){
    int pw = blockIdx.x;          // 0..256
    int ph = threadIdx.x;         // 0..511
    int kh = kmap9(ph), kw = kmap9(pw);
    int nh = (512 - kh) & 511, nw = (512 - kw) & 511;
    int s0 = kh * 512 + kw;
    int s1 = nh * 512 + nw;
    float re = 0.5f * (Hr[s0] + Hr[s1]);
    float im = 0.5f * (Hi[s0] - Hi[s1]);
    g_filter[pw * 512 + ph] = make_float2(re * INV_SCALE, im * INV_SCALE);
}

// ---------------------------------------------------------------------------
// Kernel 1: forward FFT along W (R2C); write storage positions 0..256 only.
// ---------------------------------------------------------------------------
__global__ void __launch_bounds__(256) k_fft_rows(const float* __restrict__ x){
    __shared__ float sRe[4][PL], sIm[4][PL];
    __shared__ float2 tws[512];
    int tid = threadIdx.x;
    build_tws(tws, tid);
    int line = tid >> 6, t = tid & 63;
    long long row = (long long)blockIdx.x * 4 + line;
    const float* xp = x + row * 512;

    float2 a[8];
    #pragma unroll
    for (int j = 0; j < 8; ++j) a[j] = make_float2(xp[t + 64*j], 0.0f);
    __syncthreads();   // tws ready

    fft512_fwd(a, line, t, sRe, sIm, tws);

    float2* gp = g_scratch + row * WP;
    #pragma unroll
    for (int q = 0; q < 4; ++q) gp[t + 64*q] = a[q];   // positions 0..255
    if (t == 0) gp[256] = a[4];                         // position 256 (freq 256)
}

// ---------------------------------------------------------------------------
// Kernel 2: per image, 4 columns of the half spectrum:
// fwd col FFT -> Heff multiply -> inv col FFT. 65 column groups (last has 1 valid).
// ---------------------------------------------------------------------------
__global__ void __launch_bounds__(256) k_cols(void){
    __shared__ float sRe[4][PL], sIm[4][PL];
    __shared__ float2 tws[512];
    int tid = threadIdx.x;
    build_tws(tws, tid);

    int img = blockIdx.x / 65;
    int w0  = (blockIdx.x % 65) << 2;
    float2* base = g_scratch + (long long)img * DIM_H * WP;

    // stage in: 4 adjacent cols (clamped), coalesced, conflict-free shared write
    #pragma unroll
    for (int it = 0; it < 8; ++it){
        int idx = it * 256 + tid;
        int wi = idx & 3, h = idx >> 2;
        int wc = w0 + wi; if (wc > 256) wc = 256;
        float2 v = base[(long long)h * WP + wc];
        sRe[wi][h] = v.x; sIm[wi][h] = v.y;
    }
    __syncthreads();

    int line = tid >> 6, t = tid & 63;
    float2 a[8];
    #pragma unroll
    for (int j = 0; j < 8; ++j){
        int h = t + 64*j;
        a[j] = make_float2(sRe[line][h], sIm[line][h]);
    }
    __syncthreads();   // staging consumed

    fft512_fwd(a, line, t, sRe, sIm, tws);

    int pwcol = w0 + line; if (pwcol > 256) pwcol = 256;
    const float2* frow = g_filter + (long long)pwcol * 512 + t;
    #pragma unroll
    for (int q = 0; q < 8; ++q) a[q] = cmul(a[q], frow[64*q]);

    __syncthreads();

    fft512_inv(a, line, t, sRe, sIm, tws);

    __syncthreads();
    #pragma unroll
    for (int j = 0; j < 8; ++j){
        int h = t + 64*j;
        sRe[line][h] = a[j].x; sIm[line][h] = a[j].y;
    }
    __syncthreads();

    #pragma unroll
    for (int it = 0; it < 8; ++it){
        int idx = it * 256 + tid;
        int wi = idx & 3, h = idx >> 2;
        if (w0 + wi <= 256)
            base[(long long)h * WP + w0 + wi] = make_float2(sRe[wi][h], sIm[wi][h]);
    }
}

// ---------------------------------------------------------------------------
// Kernel 3: inverse FFT along W (C2R). Load half spectrum, reconstruct the
// other half via Hermitian symmetry in shared, write real output.
// ---------------------------------------------------------------------------
__global__ void __launch_bounds__(256) k_ifft_rows(float* __restrict__ out){
    __shared__ float sRe[4][PL], sIm[4][PL];
    __shared__ float2 tws[512];
    int tid = threadIdx.x;
    build_tws(tws, tid);
    int line = tid >> 6, t = tid & 63;
    long long row = (long long)blockIdx.x * 4 + line;
    const float2* gp = g_scratch + row * WP;

    // stage half spectrum (positions 0..256) into shared, coalesced
    #pragma unroll
    for (int j = 0; j < 4; ++j){
        float2 v = gp[t + 64*j];
        sRe[line][t + 64*j] = v.x; sIm[line][t + 64*j] = v.y;
    }
    if (t == 0){ float2 v = gp[256]; sRe[line][256] = v.x; sIm[line][256] = v.y; }
    __syncthreads();

    // gather full permuted spectrum: pos p<=256 direct; else conj of mirror
    float2 a[8];
    #pragma unroll
    for (int q = 0; q < 8; ++q){
        int p = t + 64*q;
        if (p <= 256){
            a[q] = make_float2(sRe[line][p], sIm[line][p]);
        } else {
            int src = kmap9((512 - kmap9(p)) & 511);   // in [1,255]
            a[q] = make_float2(sRe[line][src], -sIm[line][src]);
        }
    }
    __syncthreads();   // staging reads done before inv FFT reuses planes

    fft512_inv(a, line, t, sRe, sIm, tws);

    float* op = out + row * 512;
    #pragma unroll
    for (int j = 0; j < 8; ++j) op[t + 64*j] = a[j].x;
}

// ---------------------------------------------------------------------------
extern "C" void kernel_launch(void* const* d_in, const int* in_sizes, int n_in,
                              void* d_out, int out_size){
    const float* x  = (const float*)d_in[0];
    const float* Hr = (const float*)d_in[1];
    const float* Hi = (const float*)d_in[2];
    float* out = (float*)d_out;

    k_bake_filter<<<257, 512>>>(Hr, Hi);
    k_fft_rows<<<NROWS / 4, 256>>>(x);
    k_cols<<<NIMG * 65, 256>>>();
    k_ifft_rows<<<NROWS / 4, 256>>>(out);
}

// round 5
// speedup vs baseline: 5.8969x; 1.1478x over previous
#include <cuda_runtime.h>

#define DIM_H 512
#define DIM_W 512
#define NIMG  128
#define NROWS (NIMG * DIM_H)           // 65536 row-lines
#define INV_SCALE (1.0f / (512.0f * 512.0f))
#define PL 584                          // shared plane pitch (>=575, ==8 mod 32)
#define WP 264                          // half-spectrum storage pitch (float2), 257 used

// Half-spectrum scratch: [img][h][pw<WP], 138 MB.
__device__ float2 g_scratch[(size_t)NIMG * DIM_H * WP];
// Baked Hermitianized filter, permuted+transposed: [pw 0..256][ph 0..511].
__device__ float2 g_filter[(size_t)257 * DIM_H];

__device__ __forceinline__ float2 cadd(float2 a, float2 b){ return make_float2(a.x+b.x, a.y+b.y); }
__device__ __forceinline__ float2 csub(float2 a, float2 b){ return make_float2(a.x-b.x, a.y-b.y); }
__device__ __forceinline__ float2 cmul(float2 a, float2 b){
    return make_float2(a.x*b.x - a.y*b.y, a.x*b.y + a.y*b.x);
}
__device__ __forceinline__ float2 cconj(float2 a){ return make_float2(a.x, -a.y); }

// storage-position <-> frequency permutation: swap low two octal digits (involution, keeps bit 8)
__device__ __forceinline__ int kmap9(int p){
    return (p & 448) | ((p & 7) << 3) | ((p >> 3) & 7);
}

// 8-point DFT, natural in/out: out[r] = sum_j in[j] * exp(S*2*pi*i*j*r/8)
template<int S>
__device__ __forceinline__ void dft8(float2* a){
    const float sg = (float)S;
    float2 e0=a[0], e1=a[2], e2=a[4], e3=a[6];
    float2 o0=a[1], o1=a[3], o2=a[5], o3=a[7];
    float2 t0=cadd(e0,e2), t1=csub(e0,e2), t2=cadd(e1,e3), t3=csub(e1,e3);
    float2 t3r = make_float2(-sg*t3.y, sg*t3.x);
    float2 E0=cadd(t0,t2), E2=csub(t0,t2), E1=cadd(t1,t3r), E3=csub(t1,t3r);
    float2 u0=cadd(o0,o2), u1=csub(o0,o2), u2=cadd(o1,o3), u3=csub(o1,o3);
    float2 u3r = make_float2(-sg*u3.y, sg*u3.x);
    float2 O0=cadd(u0,u2), O2=csub(u0,u2), O1=cadd(u1,u3r), O3=csub(u1,u3r);
    const float c = 0.70710678118654752f;
    O1 = make_float2(c*(O1.x - sg*O1.y), c*(sg*O1.x + O1.y));
    O2 = make_float2(-sg*O2.y, sg*O2.x);
    O3 = make_float2(c*(-O3.x - sg*O3.y), c*(sg*O3.x - O3.y));
    a[0]=cadd(E0,O0); a[4]=csub(E0,O0);
    a[1]=cadd(E1,O1); a[5]=csub(E1,O1);
    a[2]=cadd(E2,O2); a[6]=csub(E2,O2);
    a[3]=cadd(E3,O3); a[7]=csub(E3,O3);
}

__device__ __forceinline__ void build_tws(float2* tws, int tid){
    if (tid < 256){
        float s, c;
        sincosf(-6.283185307179586f * (float)tid / 512.0f, &s, &c);
        tws[tid] = make_float2(c, s);
        sincosf(-6.283185307179586f * (float)(tid + 256) / 512.0f, &s, &c);
        tws[tid + 256] = make_float2(c, s);
    }
}

// Forward 512-pt FFT. In: a[j] = x[t + 64*j]. Out: a[q] = X[kmap9(t + 64*q)].
__device__ __forceinline__ void fft512_fwd(float2* a, int line, int t,
                                           float (*sRe)[PL], float (*sIm)[PL],
                                           const float2* tws){
    dft8<-1>(a);
    float2 wb = tws[t], cw = wb;
    a[1] = cmul(a[1], cw);
    #pragma unroll
    for (int r = 2; r < 8; ++r){ cw = cmul(cw, wb); a[r] = cmul(a[r], cw); }
    #pragma unroll
    for (int r = 0; r < 8; ++r){ sRe[line][r*72 + t] = a[r].x; sIm[line][r*72 + t] = a[r].y; }
    __syncthreads();
    int tp = t & 7, rr = t >> 3;
    #pragma unroll
    for (int j = 0; j < 8; ++j){
        int ad = rr*72 + tp + 8*j;
        a[j] = make_float2(sRe[line][ad], sIm[line][ad]);
    }
    dft8<-1>(a);
    float2 wb2 = tws[tp*8]; cw = wb2;
    a[1] = cmul(a[1], cw);
    #pragma unroll
    for (int r = 2; r < 8; ++r){ cw = cmul(cw, wb2); a[r] = cmul(a[r], cw); }
    __syncthreads();
    #pragma unroll
    for (int r1 = 0; r1 < 8; ++r1){
        int ad = rr*72 + r1*9 + tp;
        sRe[line][ad] = a[r1].x; sIm[line][ad] = a[r1].y;
    }
    __syncthreads();
    #pragma unroll
    for (int k = 0; k < 8; ++k){
        int ad = t*9 + k;
        a[k] = make_float2(sRe[line][ad], sIm[line][ad]);
    }
    dft8<-1>(a);
}

// Inverse (unscaled) 512-pt FFT. In: a[q] = S[kmap9(t + 64*q)]. Out: a[j] = y[t + 64*j].
__device__ __forceinline__ void fft512_inv(float2* a, int line, int t,
                                           float (*sRe)[PL], float (*sIm)[PL],
                                           const float2* tws){
    dft8<1>(a);
    int tp = t & 7, rr = t >> 3;
    #pragma unroll
    for (int k = 0; k < 8; ++k){
        int ad = t*9 + k;
        sRe[line][ad] = a[k].x; sIm[line][ad] = a[k].y;
    }
    __syncthreads();
    #pragma unroll
    for (int r1 = 0; r1 < 8; ++r1){
        int ad = rr*72 + r1*9 + tp;
        a[r1] = make_float2(sRe[line][ad], sIm[line][ad]);
    }
    float2 wb2 = cconj(tws[tp*8]), cw = wb2;
    a[1] = cmul(a[1], cw);
    #pragma unroll
    for (int r = 2; r < 8; ++r){ cw = cmul(cw, wb2); a[r] = cmul(a[r], cw); }
    dft8<1>(a);
    __syncthreads();
    #pragma unroll
    for (int j = 0; j < 8; ++j){
        int ad = rr*72 + tp + 8*j;
        sRe[line][ad] = a[j].x; sIm[line][ad] = a[j].y;
    }
    __syncthreads();
    #pragma unroll
    for (int r = 0; r < 8; ++r){
        int ad = r*72 + t;
        a[r] = make_float2(sRe[line][ad], sIm[line][ad]);
    }
    float2 wb = cconj(tws[t]); cw = wb;
    a[1] = cmul(a[1], cw);
    #pragma unroll
    for (int r = 2; r < 8; ++r){ cw = cmul(cw, wb); a[r] = cmul(a[r], cw); }
    dft8<1>(a);
}

// ---------------------------------------------------------------------------
// Kernel 0: bake Hermitianized filter.
// ---------------------------------------------------------------------------
__global__ void k_bake_filter(const float* __restrict__ Hr, const float* __restrict__ Hi){
    int pw = blockIdx.x;          // 0..256
    int ph = threadIdx.x;         // 0..511
    int kh = kmap9(ph), kw = kmap9(pw);
    int nh = (512 - kh) & 511, nw = (512 - kw) & 511;
    int s0 = kh * 512 + kw;
    int s1 = nh * 512 + nw;
    float re = 0.5f * (Hr[s0] + Hr[s1]);
    float im = 0.5f * (Hi[s0] - Hi[s1]);
    g_filter[pw * 512 + ph] = make_float2(re * INV_SCALE, im * INV_SCALE);
}

// ---------------------------------------------------------------------------
// Kernel 1: paired forward FFT along W. One complex FFT per TWO real rows.
// z = x[2r] + i*x[2r+1]; untangle to half-spectra X0, X1.
// 4 pairs (8 rows) per block.
// ---------------------------------------------------------------------------
__global__ void __launch_bounds__(256) k_fft_rows(const float* __restrict__ x){
    __shared__ float sRe[4][PL], sIm[4][PL];
    __shared__ float2 tws[512];
    int tid = threadIdx.x;
    build_tws(tws, tid);
    int line = tid >> 6, t = tid & 63;
    long long pair = (long long)blockIdx.x * 4 + line;
    const float* x0 = x + pair * 1024;
    const float* x1 = x0 + 512;

    float2 a[8];
    #pragma unroll
    for (int j = 0; j < 8; ++j) a[j] = make_float2(x0[t + 64*j], x1[t + 64*j]);
    __syncthreads();   // tws ready

    fft512_fwd(a, line, t, sRe, sIm, tws);

    __syncthreads();   // FFT's last transpose reads done; planes reusable
    #pragma unroll
    for (int q = 0; q < 8; ++q){
        int p = t + 64*q;
        sRe[line][p] = a[q].x; sIm[line][p] = a[q].y;
    }
    __syncthreads();

    // Untangle: X0 = (Z[k]+conj(Z[-k]))/2, X1 = -i(Z[k]-conj(Z[-k]))/2.
    // Plane position p holds Z[kmap9(p)]; mirror position pm = kmap9(512-kmap9(p)).
    float2* g0 = g_scratch + (pair * 2) * WP;
    float2* g1 = g0 + WP;
    #pragma unroll
    for (int q = 0; q < 4; ++q){
        int p = t + 64*q;
        int pm = p ? kmap9(512 - kmap9(p)) : 0;
        float Ar = sRe[line][p],  Ai = sIm[line][p];
        float Br = sRe[line][pm], Bi = sIm[line][pm];
        g0[p] = make_float2(0.5f*(Ar + Br), 0.5f*(Ai - Bi));
        g1[p] = make_float2(0.5f*(Ai + Bi), 0.5f*(Br - Ar));
    }
    if (t == 0){   // p = 256, self-mirror
        float Ar = sRe[line][256], Ai = sIm[line][256];
        g0[256] = make_float2(Ar, 0.0f);
        g1[256] = make_float2(Ai, 0.0f);
    }
}

// ---------------------------------------------------------------------------
// Kernel 2: per image, 4 columns of the half spectrum:
// fwd col FFT -> Heff multiply -> inv col FFT.
// ---------------------------------------------------------------------------
__global__ void __launch_bounds__(256) k_cols(void){
    __shared__ float sRe[4][PL], sIm[4][PL];
    __shared__ float2 tws[512];
    int tid = threadIdx.x;
    build_tws(tws, tid);

    int img = blockIdx.x / 65;
    int w0  = (blockIdx.x % 65) << 2;
    float2* base = g_scratch + (long long)img * DIM_H * WP;

    #pragma unroll
    for (int it = 0; it < 8; ++it){
        int idx = it * 256 + tid;
        int wi = idx & 3, h = idx >> 2;
        int wc = w0 + wi; if (wc > 256) wc = 256;
        float2 v = base[(long long)h * WP + wc];
        sRe[wi][h] = v.x; sIm[wi][h] = v.y;
    }
    __syncthreads();

    int line = tid >> 6, t = tid & 63;
    float2 a[8];
    #pragma unroll
    for (int j = 0; j < 8; ++j){
        int h = t + 64*j;
        a[j] = make_float2(sRe[line][h], sIm[line][h]);
    }
    __syncthreads();

    fft512_fwd(a, line, t, sRe, sIm, tws);

    int pwcol = w0 + line; if (pwcol > 256) pwcol = 256;
    const float2* frow = g_filter + (long long)pwcol * 512 + t;
    #pragma unroll
    for (int q = 0; q < 8; ++q) a[q] = cmul(a[q], frow[64*q]);

    __syncthreads();

    fft512_inv(a, line, t, sRe, sIm, tws);

    __syncthreads();
    #pragma unroll
    for (int j = 0; j < 8; ++j){
        int h = t + 64*j;
        sRe[line][h] = a[j].x; sIm[line][h] = a[j].y;
    }
    __syncthreads();

    #pragma unroll
    for (int it = 0; it < 8; ++it){
        int idx = it * 256 + tid;
        int wi = idx & 3, h = idx >> 2;
        if (w0 + wi <= 256)
            base[(long long)h * WP + w0 + wi] = make_float2(sRe[wi][h], sIm[wi][h]);
    }
}

// ---------------------------------------------------------------------------
// Kernel 3: paired inverse FFT along W. Z = S0 + i*S1 (Hermitian-extended),
// one inverse FFT produces two real rows: y0 = Re, y1 = Im.
// ---------------------------------------------------------------------------
__global__ void __launch_bounds__(256) k_ifft_rows(float* __restrict__ out){
    __shared__ float sRe[4][PL], sIm[4][PL];
    __shared__ float2 tws[512];
    int tid = threadIdx.x;
    build_tws(tws, tid);
    int line = tid >> 6, t = tid & 63;
    long long pair = (long long)blockIdx.x * 4 + line;
    const float2* g0 = g_scratch + (pair * 2) * WP;
    const float2* g1 = g0 + WP;

    // stage both half-spectra: S0 at [0..256], S1 at [288..544] (offset 288 = 0 mod 32)
    #pragma unroll
    for (int j = 0; j < 4; ++j){
        int p = t + 64*j;
        float2 v0 = g0[p]; sRe[line][p] = v0.x;       sIm[line][p] = v0.y;
        float2 v1 = g1[p]; sRe[line][288 + p] = v1.x; sIm[line][288 + p] = v1.y;
    }
    if (t == 0){
        float2 v0 = g0[256]; sRe[line][256] = v0.x;       sIm[line][256] = v0.y;
        float2 v1 = g1[256]; sRe[line][288 + 256] = v1.x; sIm[line][288 + 256] = v1.y;
    }
    __syncthreads();

    // build permuted Z in registers:
    // p<=256: Z = S0[p] + i*S1[p] = (ar - bi, ai + br)
    // p> 256: Z = conj(S0[ps]) + i*conj(S1[ps]) = (ar + bi, br - ai)
    float2 a[8];
    #pragma unroll
    for (int q = 0; q < 8; ++q){
        int p = t + 64*q;
        if (p <= 256){
            float ar = sRe[line][p],       ai = sIm[line][p];
            float br = sRe[line][288 + p], bi = sIm[line][288 + p];
            a[q] = make_float2(ar - bi, ai + br);
        } else {
            int ps = kmap9(512 - kmap9(p));   // in [1,255]
            float ar = sRe[line][ps],       ai = sIm[line][ps];
            float br = sRe[line][288 + ps], bi = sIm[line][288 + ps];
            a[q] = make_float2(ar + bi, br - ai);
        }
    }
    __syncthreads();   // staging reads done before inv FFT reuses planes

    fft512_inv(a, line, t, sRe, sIm, tws);

    float* o0 = out + (pair * 2) * 512;
    float* o1 = o0 + 512;
    #pragma unroll
    for (int j = 0; j < 8; ++j){
        o0[t + 64*j] = a[j].x;
        o1[t + 64*j] = a[j].y;
    }
}

// ---------------------------------------------------------------------------
extern "C" void kernel_launch(void* const* d_in, const int* in_sizes, int n_in,
                              void* d_out, int out_size){
    const float* x  = (const float*)d_in[0];
    const float* Hr = (const float*)d_in[1];
    const float* Hi = (const float*)d_in[2];
    float* out = (float*)d_out;

    k_bake_filter<<<257, 512>>>(Hr, Hi);
    k_fft_rows<<<NROWS / 8, 256>>>(x);
    k_cols<<<NIMG * 65, 256>>>();
    k_ifft_rows<<<NROWS / 8, 256>>>(out);
}

// round 7
// speedup vs baseline: 6.2721x; 1.0636x over previous
#include <cuda_runtime.h>
#include <cuda_fp16.h>

#define DIM_H 512
#define DIM_W 512
#define NIMG  128
#define NROWS (NIMG * DIM_H)           // 65536 row-lines
#define INV_SCALE (1.0f / (512.0f * 512.0f))
#define PL 584                          // shared plane pitch (>=575, ==8 mod 32)
#define WP 264                          // half-spectrum storage pitch (complex), 257 used

// Half-spectrum scratch in fp16 complex: [img][h][pw<WP], 69 MB.
__device__ __half2 g_scratch[(size_t)NIMG * DIM_H * WP];
// Baked Hermitianized filter (fp32), permuted+transposed: [pw 0..256][ph 0..511].
// Includes the 1/512^2 scale AND the 0.5 untangle compensation.
__device__ float2 g_filter[(size_t)257 * DIM_H];

__device__ __forceinline__ float2 cadd(float2 a, float2 b){ return make_float2(a.x+b.x, a.y+b.y); }
__device__ __forceinline__ float2 csub(float2 a, float2 b){ return make_float2(a.x-b.x, a.y-b.y); }
__device__ __forceinline__ float2 cmul(float2 a, float2 b){
    return make_float2(a.x*b.x - a.y*b.y, a.x*b.y + a.y*b.x);
}
__device__ __forceinline__ float2 cconj(float2 a){ return make_float2(a.x, -a.y); }

__device__ __forceinline__ __half2 pack_h2(float re, float im){ return __floats2half2_rn(re, im); }
__device__ __forceinline__ float2 unpack_h2(__half2 v){ float2 f = __half22float2(v); return f; }

// storage-position <-> frequency permutation: swap low two octal digits (involution, keeps bit 8)
__device__ __forceinline__ int kmap9(int p){
    return (p & 448) | ((p & 7) << 3) | ((p >> 3) & 7);
}

// 8-point DFT, natural in/out: out[r] = sum_j in[j] * exp(S*2*pi*i*j*r/8)
template<int S>
__device__ __forceinline__ void dft8(float2* a){
    const float sg = (float)S;
    float2 e0=a[0], e1=a[2], e2=a[4], e3=a[6];
    float2 o0=a[1], o1=a[3], o2=a[5], o3=a[7];
    float2 t0=cadd(e0,e2), t1=csub(e0,e2), t2=cadd(e1,e3), t3=csub(e1,e3);
    float2 t3r = make_float2(-sg*t3.y, sg*t3.x);
    float2 E0=cadd(t0,t2), E2=csub(t0,t2), E1=cadd(t1,t3r), E3=csub(t1,t3r);
    float2 u0=cadd(o0,o2), u1=csub(o0,o2), u2=cadd(o1,o3), u3=csub(o1,o3);
    float2 u3r = make_float2(-sg*u3.y, sg*u3.x);
    float2 O0=cadd(u0,u2), O2=csub(u0,u2), O1=cadd(u1,u3r), O3=csub(u1,u3r);
    const float c = 0.70710678118654752f;
    O1 = make_float2(c*(O1.x - sg*O1.y), c*(sg*O1.x + O1.y));
    O2 = make_float2(-sg*O2.y, sg*O2.x);
    O3 = make_float2(c*(-O3.x - sg*O3.y), c*(sg*O3.x - O3.y));
    a[0]=cadd(E0,O0); a[4]=csub(E0,O0);
    a[1]=cadd(E1,O1); a[5]=csub(E1,O1);
    a[2]=cadd(E2,O2); a[6]=csub(E2,O2);
    a[3]=cadd(E3,O3); a[7]=csub(E3,O3);
}

__device__ __forceinline__ void build_tws(float2* tws, int tid){
    if (tid < 256){
        float s, c;
        sincosf(-6.283185307179586f * (float)tid / 512.0f, &s, &c);
        tws[tid] = make_float2(c, s);
        sincosf(-6.283185307179586f * (float)(tid + 256) / 512.0f, &s, &c);
        tws[tid + 256] = make_float2(c, s);
    }
}

// Forward 512-pt FFT. In: a[j] = x[t + 64*j]. Out: a[q] = X[kmap9(t + 64*q)].
__device__ __forceinline__ void fft512_fwd(float2* a, int line, int t,
                                           float (*sRe)[PL], float (*sIm)[PL],
                                           const float2* tws){
    dft8<-1>(a);
    float2 wb = tws[t], cw = wb;
    a[1] = cmul(a[1], cw);
    #pragma unroll
    for (int r = 2; r < 8; ++r){ cw = cmul(cw, wb); a[r] = cmul(a[r], cw); }
    #pragma unroll
    for (int r = 0; r < 8; ++r){ sRe[line][r*72 + t] = a[r].x; sIm[line][r*72 + t] = a[r].y; }
    __syncthreads();
    int tp = t & 7, rr = t >> 3;
    #pragma unroll
    for (int j = 0; j < 8; ++j){
        int ad = rr*72 + tp + 8*j;
        a[j] = make_float2(sRe[line][ad], sIm[line][ad]);
    }
    dft8<-1>(a);
    float2 wb2 = tws[tp*8]; cw = wb2;
    a[1] = cmul(a[1], cw);
    #pragma unroll
    for (int r = 2; r < 8; ++r){ cw = cmul(cw, wb2); a[r] = cmul(a[r], cw); }
    __syncthreads();
    #pragma unroll
    for (int r1 = 0; r1 < 8; ++r1){
        int ad = rr*72 + r1*9 + tp;
        sRe[line][ad] = a[r1].x; sIm[line][ad] = a[r1].y;
    }
    __syncthreads();
    #pragma unroll
    for (int k = 0; k < 8; ++k){
        int ad = t*9 + k;
        a[k] = make_float2(sRe[line][ad], sIm[line][ad]);
    }
    dft8<-1>(a);
}

// Inverse (unscaled) 512-pt FFT. In: a[q] = S[kmap9(t + 64*q)]. Out: a[j] = y[t + 64*j].
__device__ __forceinline__ void fft512_inv(float2* a, int line, int t,
                                           float (*sRe)[PL], float (*sIm)[PL],
                                           const float2* tws){
    dft8<1>(a);
    int tp = t & 7, rr = t >> 3;
    #pragma unroll
    for (int k = 0; k < 8; ++k){
        int ad = t*9 + k;
        sRe[line][ad] = a[k].x; sIm[line][ad] = a[k].y;
    }
    __syncthreads();
    #pragma unroll
    for (int r1 = 0; r1 < 8; ++r1){
        int ad = rr*72 + r1*9 + tp;
        a[r1] = make_float2(sRe[line][ad], sIm[line][ad]);
    }
    float2 wb2 = cconj(tws[tp*8]), cw = wb2;
    a[1] = cmul(a[1], cw);
    #pragma unroll
    for (int r = 2; r < 8; ++r){ cw = cmul(cw, wb2); a[r] = cmul(a[r], cw); }
    dft8<1>(a);
    __syncthreads();
    #pragma unroll
    for (int j = 0; j < 8; ++j){
        int ad = rr*72 + tp + 8*j;
        sRe[line][ad] = a[j].x; sIm[line][ad] = a[j].y;
    }
    __syncthreads();
    #pragma unroll
    for (int r = 0; r < 8; ++r){
        int ad = r*72 + t;
        a[r] = make_float2(sRe[line][ad], sIm[line][ad]);
    }
    float2 wb = cconj(tws[t]); cw = wb;
    a[1] = cmul(a[1], cw);
    #pragma unroll
    for (int r = 2; r < 8; ++r){ cw = cmul(cw, wb); a[r] = cmul(a[r], cw); }
    dft8<1>(a);
}

// ---------------------------------------------------------------------------
// Kernel 0: bake Hermitianized filter.
// Stored value = Heff * INV_SCALE * 0.5, where Heff = (H[k] + conj(H[-k]))/2.
// The extra 0.5 compensates the untangle in k_fft_rows storing 2x spectra.
// = 0.25 * (H[s0] + conj(H[s1])) * INV_SCALE
// ---------------------------------------------------------------------------
__global__ void k_bake_filter(const float* __restrict__ Hr, const float* __restrict__ Hi){
    int pw = blockIdx.x;          // 0..256
    int ph = threadIdx.x;         // 0..511
    int kh = kmap9(ph), kw = kmap9(pw);
    int nh = (512 - kh) & 511, nw = (512 - kw) & 511;
    int s0 = kh * 512 + kw;
    int s1 = nh * 512 + nw;
    float re = 0.25f * (Hr[s0] + Hr[s1]);
    float im = 0.25f * (Hi[s0] - Hi[s1]);
    g_filter[pw * 512 + ph] = make_float2(re * INV_SCALE, im * INV_SCALE);
}

// ---------------------------------------------------------------------------
// Kernel 1: paired forward FFT along W. One complex FFT per TWO real rows.
// Untangle WITHOUT the 0.5 (folded into filter); store fp16.
// ---------------------------------------------------------------------------
__global__ void __launch_bounds__(256) k_fft_rows(const float* __restrict__ x){
    __shared__ float sRe[4][PL], sIm[4][PL];
    __shared__ float2 tws[512];
    int tid = threadIdx.x;
    build_tws(tws, tid);
    int line = tid >> 6, t = tid & 63;
    long long pair = (long long)blockIdx.x * 4 + line;
    const float* x0 = x + pair * 1024;
    const float* x1 = x0 + 512;

    float2 a[8];
    #pragma unroll
    for (int j = 0; j < 8; ++j) a[j] = make_float2(x0[t + 64*j], x1[t + 64*j]);
    __syncthreads();   // tws ready

    fft512_fwd(a, line, t, sRe, sIm, tws);

    __syncthreads();
    #pragma unroll
    for (int q = 0; q < 8; ++q){
        int p = t + 64*q;
        sRe[line][p] = a[q].x; sIm[line][p] = a[q].y;
    }
    __syncthreads();

    __half2* g0 = g_scratch + (pair * 2) * WP;
    __half2* g1 = g0 + WP;
    #pragma unroll
    for (int q = 0; q < 4; ++q){
        int p = t + 64*q;
        int pm = p ? kmap9(512 - kmap9(p)) : 0;
        float Ar = sRe[line][p],  Ai = sIm[line][p];
        float Br = sRe[line][pm], Bi = sIm[line][pm];
        g0[p] = pack_h2(Ar + Br, Ai - Bi);
        g1[p] = pack_h2(Ai + Bi, Br - Ar);
    }
    if (t == 0){   // p = 256, self-mirror
        float Ar = sRe[line][256], Ai = sIm[line][256];
        g0[256] = pack_h2(2.0f * Ar, 0.0f);
        g1[256] = pack_h2(2.0f * Ai, 0.0f);
    }
}

// ---------------------------------------------------------------------------
// Kernel 2: per image, 4 columns of the half spectrum:
// fwd col FFT -> Heff multiply -> inv col FFT. fp16 in/out.
// ---------------------------------------------------------------------------
__global__ void __launch_bounds__(256) k_cols(void){
    __shared__ float sRe[4][PL], sIm[4][PL];
    __shared__ float2 tws[512];
    int tid = threadIdx.x;
    build_tws(tws, tid);

    int img = blockIdx.x / 65;
    int w0  = (blockIdx.x % 65) << 2;
    __half2* base = g_scratch + (long long)img * DIM_H * WP;

    #pragma unroll
    for (int it = 0; it < 8; ++it){
        int idx = it * 256 + tid;
        int wi = idx & 3, h = idx >> 2;
        int wc = w0 + wi; if (wc > 256) wc = 256;
        float2 v = unpack_h2(base[(long long)h * WP + wc]);
        sRe[wi][h] = v.x; sIm[wi][h] = v.y;
    }
    __syncthreads();

    int line = tid >> 6, t = tid & 63;
    float2 a[8];
    #pragma unroll
    for (int j = 0; j < 8; ++j){
        int h = t + 64*j;
        a[j] = make_float2(sRe[line][h], sIm[line][h]);
    }
    __syncthreads();

    fft512_fwd(a, line, t, sRe, sIm, tws);

    int pwcol = w0 + line; if (pwcol > 256) pwcol = 256;
    const float2* frow = g_filter + (long long)pwcol * 512 + t;
    #pragma unroll
    for (int q = 0; q < 8; ++q) a[q] = cmul(a[q], frow[64*q]);

    __syncthreads();

    fft512_inv(a, line, t, sRe, sIm, tws);

    __syncthreads();
    #pragma unroll
    for (int j = 0; j < 8; ++j){
        int h = t + 64*j;
        sRe[line][h] = a[j].x; sIm[line][h] = a[j].y;
    }
    __syncthreads();

    #pragma unroll
    for (int it = 0; it < 8; ++it){
        int idx = it * 256 + tid;
        int wi = idx & 3, h = idx >> 2;
        if (w0 + wi <= 256)
            base[(long long)h * WP + w0 + wi] = pack_h2(sRe[wi][h], sIm[wi][h]);
    }
}

// ---------------------------------------------------------------------------
// Kernel 3: paired inverse FFT along W (C2R x2). fp16 in, fp32 out.
// ---------------------------------------------------------------------------
__global__ void __launch_bounds__(256) k_ifft_rows(float* __restrict__ out){
    __shared__ float sRe[4][PL], sIm[4][PL];
    __shared__ float2 tws[512];
    int tid = threadIdx.x;
    build_tws(tws, tid);
    int line = tid >> 6, t = tid & 63;
    long long pair = (long long)blockIdx.x * 4 + line;
    const __half2* g0 = g_scratch + (pair * 2) * WP;
    const __half2* g1 = g0 + WP;

    // stage both half-spectra: S0 at [0..256], S1 at [288..544]
    #pragma unroll
    for (int j = 0; j < 4; ++j){
        int p = t + 64*j;
        float2 v0 = unpack_h2(g0[p]); sRe[line][p] = v0.x;       sIm[line][p] = v0.y;
        float2 v1 = unpack_h2(g1[p]); sRe[line][288 + p] = v1.x; sIm[line][288 + p] = v1.y;
    }
    if (t == 0){
        float2 v0 = unpack_h2(g0[256]); sRe[line][256] = v0.x;       sIm[line][256] = v0.y;
        float2 v1 = unpack_h2(g1[256]); sRe[line][288 + 256] = v1.x; sIm[line][288 + 256] = v1.y;
    }
    __syncthreads();

    float2 a[8];
    #pragma unroll
    for (int q = 0; q < 8; ++q){
        int p = t + 64*q;
        if (p <= 256){
            float ar = sRe[line][p],       ai = sIm[line][p];
            float br = sRe[line][288 + p], bi = sIm[line][288 + p];
            a[q] = make_float2(ar - bi, ai + br);
        } else {
            int ps = kmap9(512 - kmap9(p));   // in [1,255]
            float ar = sRe[line][ps],       ai = sIm[line][ps];
            float br = sRe[line][288 + ps], bi = sIm[line][288 + ps];
            a[q] = make_float2(ar + bi, br - ai);
        }
    }
    __syncthreads();

    fft512_inv(a, line, t, sRe, sIm, tws);

    float* o0 = out + (pair * 2) * 512;
    float* o1 = o0 + 512;
    #pragma unroll
    for (int j = 0; j < 8; ++j){
        o0[t + 64*j] = a[j].x;
        o1[t + 64*j] = a[j].y;
    }
}

// ---------------------------------------------------------------------------
extern "C" void kernel_launch(void* const* d_in, const int* in_sizes, int n_in,
                              void* d_out, int out_size){
    const float* x  = (const float*)d_in[0];
    const float* Hr = (const float*)d_in[1];
    const float* Hi = (const float*)d_in[2];
    float* out = (float*)d_out;

    k_bake_filter<<<257, 512>>>(Hr, Hi);
    k_fft_rows<<<NROWS / 8, 256>>>(x);
    k_cols<<<NIMG * 65, 256>>>();
    k_ifft_rows<<<NROWS / 8, 256>>>(out);
}

// round 8
// speedup vs baseline: 7.0641x; 1.1263x over previous
#include <cuda_runtime.h>
#include <cuda_fp16.h>

#define DIM_H 512
#define DIM_W 512
#define NIMG  128
#define NROWS (NIMG * DIM_H)           // 65536 row-lines
#define INV_SCALE (1.0f / (512.0f * 512.0f))
#define PLX 580                         // float2 plane pitch: >=576, ==4 mod 16
#define WP 264                          // half-spectrum storage pitch (complex), 257 used

// Half-spectrum scratch in fp16 complex: [img][h][pw<WP], 69 MB.
__device__ __half2 g_scratch[(size_t)NIMG * DIM_H * WP];
// Baked Hermitianized filter (fp32): [pw 0..256][ph 0..511], scale+untangle folded.
__device__ float2 g_filter[(size_t)257 * DIM_H];

__device__ __forceinline__ float2 cadd(float2 a, float2 b){ return make_float2(a.x+b.x, a.y+b.y); }
__device__ __forceinline__ float2 csub(float2 a, float2 b){ return make_float2(a.x-b.x, a.y-b.y); }
__device__ __forceinline__ float2 cmul(float2 a, float2 b){
    return make_float2(a.x*b.x - a.y*b.y, a.x*b.y + a.y*b.x);
}
__device__ __forceinline__ float2 cconj(float2 a){ return make_float2(a.x, -a.y); }

__device__ __forceinline__ __half2 pack_h2(float re, float im){ return __floats2half2_rn(re, im); }
__device__ __forceinline__ float2 unpack_h2(__half2 v){ return __half22float2(v); }

// storage-position <-> frequency permutation: swap low two octal digits (involution, keeps bit 8)
__device__ __forceinline__ int kmap9(int p){
    return (p & 448) | ((p & 7) << 3) | ((p >> 3) & 7);
}

// 8-point DFT, natural in/out: out[r] = sum_j in[j] * exp(S*2*pi*i*j*r/8)
template<int S>
__device__ __forceinline__ void dft8(float2* a){
    const float sg = (float)S;
    float2 e0=a[0], e1=a[2], e2=a[4], e3=a[6];
    float2 o0=a[1], o1=a[3], o2=a[5], o3=a[7];
    float2 t0=cadd(e0,e2), t1=csub(e0,e2), t2=cadd(e1,e3), t3=csub(e1,e3);
    float2 t3r = make_float2(-sg*t3.y, sg*t3.x);
    float2 E0=cadd(t0,t2), E2=csub(t0,t2), E1=cadd(t1,t3r), E3=csub(t1,t3r);
    float2 u0=cadd(o0,o2), u1=csub(o0,o2), u2=cadd(o1,o3), u3=csub(o1,o3);
    float2 u3r = make_float2(-sg*u3.y, sg*u3.x);
    float2 O0=cadd(u0,u2), O2=csub(u0,u2), O1=cadd(u1,u3r), O3=csub(u1,u3r);
    const float c = 0.70710678118654752f;
    O1 = make_float2(c*(O1.x - sg*O1.y), c*(sg*O1.x + O1.y));
    O2 = make_float2(-sg*O2.y, sg*O2.x);
    O3 = make_float2(c*(-O3.x - sg*O3.y), c*(sg*O3.x - O3.y));
    a[0]=cadd(E0,O0); a[4]=csub(E0,O0);
    a[1]=cadd(E1,O1); a[5]=csub(E1,O1);
    a[2]=cadd(E2,O2); a[6]=csub(E2,O2);
    a[3]=cadd(E3,O3); a[7]=csub(E3,O3);
}

// Apply w^r to a[r], r=1..7, via binary powering (dep depth 3).
__device__ __forceinline__ void apply7(float2* a, float2 w1){
    float2 w2 = cmul(w1, w1);
    float2 w3 = cmul(w2, w1);
    float2 w4 = cmul(w2, w2);
    float2 w5 = cmul(w3, w2);
    float2 w6 = cmul(w3, w3);
    float2 w7 = cmul(w4, w3);
    a[1] = cmul(a[1], w1); a[2] = cmul(a[2], w2); a[3] = cmul(a[3], w3);
    a[4] = cmul(a[4], w4); a[5] = cmul(a[5], w5); a[6] = cmul(a[6], w6);
    a[7] = cmul(a[7], w7);
}

// Only entries 0..63 are ever needed: tws[k] = exp(-2*pi*i*k/512)
__device__ __forceinline__ void build_tws(float2* tws, int tid){
    if (tid < 64){
        float s, c;
        sincosf(-6.283185307179586f * (float)tid / 512.0f, &s, &c);
        tws[tid] = make_float2(c, s);
    }
}

// Forward 512-pt FFT. In: a[j] = x[t + 64*j]. Out: a[q] = X[kmap9(t + 64*q)].
__device__ __forceinline__ void fft512_fwd(float2* a, float2* plane, int t,
                                           const float2* tws){
    dft8<-1>(a);
    apply7(a, tws[t]);
    #pragma unroll
    for (int r = 0; r < 8; ++r) plane[r*72 + t] = a[r];
    __syncthreads();
    int tp = t & 7, rr = t >> 3;
    #pragma unroll
    for (int j = 0; j < 8; ++j) a[j] = plane[rr*72 + tp + 8*j];
    dft8<-1>(a);
    apply7(a, tws[tp*8]);
    __syncthreads();
    #pragma unroll
    for (int r1 = 0; r1 < 8; ++r1) plane[rr*72 + r1*9 + tp] = a[r1];
    __syncthreads();
    #pragma unroll
    for (int k = 0; k < 8; ++k) a[k] = plane[t*9 + k];
    dft8<-1>(a);
}

// Inverse (unscaled) 512-pt FFT. In: a[q] = S[kmap9(t + 64*q)]. Out: a[j] = y[t + 64*j].
__device__ __forceinline__ void fft512_inv(float2* a, float2* plane, int t,
                                           const float2* tws){
    dft8<1>(a);
    int tp = t & 7, rr = t >> 3;
    #pragma unroll
    for (int k = 0; k < 8; ++k) plane[t*9 + k] = a[k];
    __syncthreads();
    #pragma unroll
    for (int r1 = 0; r1 < 8; ++r1) a[r1] = plane[rr*72 + r1*9 + tp];
    apply7(a, cconj(tws[tp*8]));
    dft8<1>(a);
    __syncthreads();
    #pragma unroll
    for (int j = 0; j < 8; ++j) plane[rr*72 + tp + 8*j] = a[j];
    __syncthreads();
    #pragma unroll
    for (int r = 0; r < 8; ++r) a[r] = plane[r*72 + t];
    apply7(a, cconj(tws[t]));
    dft8<1>(a);
}

// ---------------------------------------------------------------------------
// Kernel 0: bake Hermitianized filter.
// Stored = 0.25 * (H[s0] + conj(H[s1])) * INV_SCALE  (0.5 Hermitianize * 0.5 untangle)
// ---------------------------------------------------------------------------
__global__ void k_bake_filter(const float* __restrict__ Hr, const float* __restrict__ Hi){
    int pw = blockIdx.x;          // 0..256
    int ph = threadIdx.x;         // 0..511
    int kh = kmap9(ph), kw = kmap9(pw);
    int nh = (512 - kh) & 511, nw = (512 - kw) & 511;
    int s0 = kh * 512 + kw;
    int s1 = nh * 512 + nw;
    float re = 0.25f * (Hr[s0] + Hr[s1]);
    float im = 0.25f * (Hi[s0] - Hi[s1]);
    g_filter[pw * 512 + ph] = make_float2(re * INV_SCALE, im * INV_SCALE);
}

// ---------------------------------------------------------------------------
// Kernel 1: paired forward FFT along W (2 real rows / complex FFT), fp16 out.
// ---------------------------------------------------------------------------
__global__ void __launch_bounds__(256) k_fft_rows(const float* __restrict__ x){
    __shared__ float2 sD[4][PLX];
    __shared__ float2 tws[64];
    int tid = threadIdx.x;
    build_tws(tws, tid);
    int line = tid >> 6, t = tid & 63;
    long long pair = (long long)blockIdx.x * 4 + line;
    const float* x0 = x + pair * 1024;
    const float* x1 = x0 + 512;

    float2 a[8];
    #pragma unroll
    for (int j = 0; j < 8; ++j) a[j] = make_float2(x0[t + 64*j], x1[t + 64*j]);
    __syncthreads();   // tws ready

    fft512_fwd(a, sD[line], t, tws);

    __syncthreads();
    #pragma unroll
    for (int q = 0; q < 8; ++q) sD[line][t + 64*q] = a[q];
    __syncthreads();

    __half2* g0 = g_scratch + (pair * 2) * WP;
    __half2* g1 = g0 + WP;
    #pragma unroll
    for (int q = 0; q < 4; ++q){
        int p = t + 64*q;
        int pm = p ? kmap9(512 - kmap9(p)) : 0;
        float2 A = sD[line][p];
        float2 B = sD[line][pm];
        g0[p] = pack_h2(A.x + B.x, A.y - B.y);
        g1[p] = pack_h2(A.y + B.y, B.x - A.x);
    }
    if (t == 0){   // p = 256, self-mirror
        float2 A = sD[line][256];
        g0[256] = pack_h2(2.0f * A.x, 0.0f);
        g1[256] = pack_h2(2.0f * A.y, 0.0f);
    }
}

// ---------------------------------------------------------------------------
// Kernel 2: per image, 4 columns of the half spectrum:
// fwd col FFT -> Heff multiply -> inv col FFT. fp16 in/out.
// ---------------------------------------------------------------------------
__global__ void __launch_bounds__(256) k_cols(void){
    __shared__ float2 sD[4][PLX];
    __shared__ float2 tws[64];
    int tid = threadIdx.x;
    build_tws(tws, tid);

    int img = blockIdx.x / 65;
    int w0  = (blockIdx.x % 65) << 2;
    __half2* base = g_scratch + (long long)img * DIM_H * WP;

    #pragma unroll
    for (int it = 0; it < 8; ++it){
        int idx = it * 256 + tid;
        int wi = idx & 3, h = idx >> 2;
        int wc = w0 + wi; if (wc > 256) wc = 256;
        sD[wi][h] = unpack_h2(base[(long long)h * WP + wc]);
    }
    __syncthreads();

    int line = tid >> 6, t = tid & 63;
    float2 a[8];
    #pragma unroll
    for (int j = 0; j < 8; ++j) a[j] = sD[line][t + 64*j];
    __syncthreads();   // staging consumed

    fft512_fwd(a, sD[line], t, tws);

    int pwcol = w0 + line; if (pwcol > 256) pwcol = 256;
    const float2* frow = g_filter + (long long)pwcol * 512 + t;
    #pragma unroll
    for (int q = 0; q < 8; ++q) a[q] = cmul(a[q], frow[64*q]);

    __syncthreads();

    fft512_inv(a, sD[line], t, tws);

    __syncthreads();
    #pragma unroll
    for (int j = 0; j < 8; ++j) sD[line][t + 64*j] = a[j];
    __syncthreads();

    #pragma unroll
    for (int it = 0; it < 8; ++it){
        int idx = it * 256 + tid;
        int wi = idx & 3, h = idx >> 2;
        if (w0 + wi <= 256){
            float2 v = sD[wi][h];
            base[(long long)h * WP + w0 + wi] = pack_h2(v.x, v.y);
        }
    }
}

// ---------------------------------------------------------------------------
// Kernel 3: paired inverse FFT along W (C2R x2). fp16 in, fp32 out.
// ---------------------------------------------------------------------------
__global__ void __launch_bounds__(256) k_ifft_rows(float* __restrict__ out){
    __shared__ float2 sD[4][PLX];
    __shared__ float2 tws[64];
    int tid = threadIdx.x;
    build_tws(tws, tid);
    int line = tid >> 6, t = tid & 63;
    long long pair = (long long)blockIdx.x * 4 + line;
    const __half2* g0 = g_scratch + (pair * 2) * WP;
    const __half2* g1 = g0 + WP;

    // stage both half-spectra: S0 at [0..256], S1 at [288..544]
    #pragma unroll
    for (int j = 0; j < 4; ++j){
        int p = t + 64*j;
        sD[line][p]       = unpack_h2(g0[p]);
        sD[line][288 + p] = unpack_h2(g1[p]);
    }
    if (t == 0){
        sD[line][256]       = unpack_h2(g0[256]);
        sD[line][288 + 256] = unpack_h2(g1[256]);
    }
    __syncthreads();

    // build permuted Z in registers:
    // p<=256: Z = S0[p] + i*S1[p];  p>256: Z = conj(S0[ps]) + i*conj(S1[ps])
    float2 a[8];
    #pragma unroll
    for (int q = 0; q < 8; ++q){
        int p = t + 64*q;
        if (p <= 256){
            float2 A = sD[line][p];
            float2 B = sD[line][288 + p];
            a[q] = make_float2(A.x - B.y, A.y + B.x);
        } else {
            int ps = kmap9(512 - kmap9(p));   // in [1,255]
            float2 A = sD[line][ps];
            float2 B = sD[line][288 + ps];
            a[q] = make_float2(A.x + B.y, B.x - A.y);
        }
    }
    __syncthreads();   // staging reads done before inv FFT reuses plane

    fft512_inv(a, sD[line], t, tws);

    float* o0 = out + (pair * 2) * 512;
    float* o1 = o0 + 512;
    #pragma unroll
    for (int j = 0; j < 8; ++j){
        o0[t + 64*j] = a[j].x;
        o1[t + 64*j] = a[j].y;
    }
}

// ---------------------------------------------------------------------------
extern "C" void kernel_launch(void* const* d_in, const int* in_sizes, int n_in,
                              void* d_out, int out_size){
    const float* x  = (const float*)d_in[0];
    const float* Hr = (const float*)d_in[1];
    const float* Hi = (const float*)d_in[2];
    float* out = (float*)d_out;

    k_bake_filter<<<257, 512>>>(Hr, Hi);
    k_fft_rows<<<NROWS / 8, 256>>>(x);
    k_cols<<<NIMG * 65, 256>>>();
    k_ifft_rows<<<NROWS / 8, 256>>>(out);
}